// round 14
// baseline (speedup 1.0000x reference)
#include <cuda_runtime.h>
#include <cuda_fp16.h>
#include <math.h>

// ---------------- problem constants ----------------
#define HS    1024
#define NH    8
#define HD    128
#define BATCH 16
#define SEQ   2400
#define NBLK  200
#define NQUAD 50
#define MROWS (BATCH*SEQ)          // 38400

#define CHUNKQ 12
#define PASTQ  12
#define CTXQ   24
#define PQ     25

#define Q_SCALE_F (0.08838834764831845f / 0.6931471805599453f)
#define K_SCALE_F (1.3132616875182228f / 0.6931471805599453f)

// ---------------- scratch ----------------
__device__ __half g_qh [(size_t)MROWS * HS];
__device__ __half g_kh [(size_t)MROWS * HS];
__device__ __half g_vh [(size_t)MROWS * HS];
__device__ __half g_aoh[(size_t)MROWS * HS];
__device__ __half g_xh [(size_t)MROWS * HS];
__device__ __half g_wth[4][(size_t)HS * HS];
__device__ __half g_relkh[PQ * HS];

__device__ __forceinline__ unsigned cvta_smem(const void* p) {
    return (unsigned)__cvta_generic_to_shared(p);
}
__device__ __forceinline__ void cp_async16(void* dst, const void* src) {
    asm volatile("cp.async.cg.shared.global [%0], [%1], 16;\n"
                 :: "r"(cvta_smem(dst)), "l"(src));
}
__device__ __forceinline__ void cp_commit() {
    asm volatile("cp.async.commit_group;\n");
}
__device__ __forceinline__ void ldm_x4(unsigned& r0, unsigned& r1,
                                       unsigned& r2, unsigned& r3, unsigned a) {
    asm volatile("ldmatrix.sync.aligned.m8n8.x4.shared.b16 {%0,%1,%2,%3}, [%4];\n"
                 : "=r"(r0), "=r"(r1), "=r"(r2), "=r"(r3) : "r"(a));
}
__device__ __forceinline__ void ldm_x2(unsigned& r0, unsigned& r1, unsigned a) {
    asm volatile("ldmatrix.sync.aligned.m8n8.x2.shared.b16 {%0,%1}, [%2];\n"
                 : "=r"(r0), "=r"(r1) : "r"(a));
}
__device__ __forceinline__ void ldm_x2_trans(unsigned& r0, unsigned& r1, unsigned a) {
    asm volatile("ldmatrix.sync.aligned.m8n8.x2.trans.shared.b16 {%0,%1}, [%2];\n"
                 : "=r"(r0), "=r"(r1) : "r"(a));
}
__device__ __forceinline__ void mma16816(float* d, unsigned a0, unsigned a1,
                                         unsigned a2, unsigned a3,
                                         unsigned b0, unsigned b1) {
    asm volatile(
        "mma.sync.aligned.m16n8k16.row.col.f32.f16.f16.f32 "
        "{%0,%1,%2,%3}, {%4,%5,%6,%7}, {%8,%9}, {%0,%1,%2,%3};\n"
        : "+f"(d[0]), "+f"(d[1]), "+f"(d[2]), "+f"(d[3])
        : "r"(a0), "r"(a1), "r"(a2), "r"(a3), "r"(b0), "r"(b1));
}
#define BARS(id) asm volatile("bar.sync %0, %1;" :: "r"(id), "r"(128) : "memory")

// ---------------- unified prep: x->half (blocks 0..37599), W^T (after) ----
#define XBLOCKS (MROWS * HS / 1024)      // 38400
__global__ __launch_bounds__(256) void prep_all(
    const float* __restrict__ x,
    const float* __restrict__ Wq, const float* __restrict__ Wk,
    const float* __restrict__ Wv, const float* __restrict__ Wpost)
{
    const int t = threadIdx.x;
    if (blockIdx.x < XBLOCKS) {
        size_t i = ((size_t)blockIdx.x * 256 + t) * 4;
        float4 v = *(const float4*)(x + i);
        *(__half2*)(g_xh + i)     = __floats2half2_rn(v.x, v.y);
        *(__half2*)(g_xh + i + 2) = __floats2half2_rn(v.z, v.w);
        return;
    }
    // W transpose: 4096 blocks, each a 32x32 tile
    __shared__ float tile[32][33];
    int bid2 = blockIdx.x - XBLOCKS;
    int w = bid2 >> 10;
    int ti = bid2 & 1023;
    int bx = ti & 31, by = ti >> 5;
    const float* src = (w == 0) ? Wq : (w == 1) ? Wk : (w == 2) ? Wv : Wpost;
    const int tx = t & 31, ty = t >> 5;    // 32 x 8
    const int x0 = bx * 32, y0 = by * 32;
#pragma unroll
    for (int i = 0; i < 32; i += 8)
        tile[ty + i][tx] = src[(size_t)(y0 + ty + i) * HS + x0 + tx];
    __syncthreads();
    __half* dst = g_wth[w];
#pragma unroll
    for (int i = 0; i < 32; i += 8)
        dst[(size_t)(x0 + ty + i) * HS + y0 + tx] = __float2half(tile[tx][ty + i]);
}

// ------------ fp16 tensor-core GEMM: 128x128, BK=64, 3-stage ring ---------
#define BM 128
#define BN 128
#define BKH 64
#define BKP 72
#define KTILES (HS / BKH)                 // 16
#define NSTAGE 3
#define OP_ST (BM * BKP)
#define STG   (2 * OP_ST)
#define SMEM_DYN (NSTAGE * STG * 2)       // 110592 bytes

extern __shared__ __align__(16) unsigned char dynpool[];

__device__ __forceinline__ void gemm_fill(
    __half* base, int slot, int ktile, int t,
    const __half* __restrict__ Abase, const __half* __restrict__ Bbase)
{
    const __half* Ap = Abase + ktile * BKH;
    const __half* Bp = Bbase + ktile * BKH;
    __half* Ad = base + slot * STG;
    __half* Bd = Ad + OP_ST;
#pragma unroll
    for (int i = 0; i < 4; i++) {
        int q = t + i * 256;
        int row = q >> 3, c = (q & 7) * 8;
        cp_async16(Ad + (size_t)row * BKP + c, Ap + (size_t)row * HS + c);
        cp_async16(Bd + (size_t)row * BKP + c, Bp + (size_t)row * HS + c);
    }
    cp_commit();
}

__device__ __forceinline__ void gemm_fp16(
    const __half* __restrict__ A, const __half* __restrict__ Wt,
    void* __restrict__ Cv, int outHalf,
    int scalemode, const float* __restrict__ pds, float cscale)
{
    __half* Sb = (__half*)dynpool;

    const int t    = threadIdx.x;
    const int lane = t & 31;
    const int warp = t >> 5;
    const int wrow = (warp & 1) * 64;
    const int wcol = (warp >> 1) * 32;
    const int g    = lane >> 2;
    const int tg   = lane & 3;

    const int m0 = blockIdx.y * BM;
    const int n0 = blockIdx.x * BN;

    const __half* Abase = A  + (size_t)m0 * HS;
    const __half* Bbase = Wt + (size_t)n0 * HS;

    const int aRow = (lane & 7) + ((lane >> 3) & 1) * 8;
    const int aCol = ((lane >> 4) & 1) * 8;
    const int bRow = (lane & 7) + ((lane >> 4) & 1) * 8;
    const int bCol = ((lane >> 3) & 1) * 8;

    float acc[4][4][4];
#pragma unroll
    for (int i = 0; i < 4; i++)
#pragma unroll
        for (int j = 0; j < 4; j++)
#pragma unroll
            for (int c = 0; c < 4; c++) acc[i][j][c] = 0.f;

    gemm_fill(Sb, 0, 0, t, Abase, Bbase);
    gemm_fill(Sb, 1, 1, t, Abase, Bbase);

    for (int tile = 0; tile < KTILES; ++tile) {
        if (tile < KTILES - 1) asm volatile("cp.async.wait_group 1;\n");
        else                   asm volatile("cp.async.wait_group 0;\n");
        __syncthreads();

        if (tile + 2 < KTILES)
            gemm_fill(Sb, (tile + 2) % NSTAGE, tile + 2, t, Abase, Bbase);

        const int bo = (tile % NSTAGE) * STG;
        __half* As = Sb + bo;
        __half* Bs = As + OP_ST;
#pragma unroll
        for (int kk = 0; kk < 4; kk++) {
            const int kh = kk * 16;
            unsigned af[4][4], bf[4][2];
#pragma unroll
            for (int mt = 0; mt < 4; mt++) {
                unsigned a = cvta_smem(As +
                    (size_t)(wrow + mt * 16 + aRow) * BKP + kh + aCol);
                ldm_x4(af[mt][0], af[mt][1], af[mt][2], af[mt][3], a);
            }
#pragma unroll
            for (int p = 0; p < 2; p++) {
                unsigned a = cvta_smem(Bs +
                    (size_t)(wcol + p * 16 + bRow) * BKP + kh + bCol);
                ldm_x4(bf[2*p][0], bf[2*p][1], bf[2*p+1][0], bf[2*p+1][1], a);
            }
#pragma unroll
            for (int mt = 0; mt < 4; mt++)
#pragma unroll
                for (int nt = 0; nt < 4; nt++)
                    mma16816(acc[mt][nt], af[mt][0], af[mt][1], af[mt][2],
                             af[mt][3], bf[nt][0], bf[nt][1]);
        }
    }

    float sc[4][2];
#pragma unroll
    for (int nt = 0; nt < 4; nt++) {
#pragma unroll
        for (int ci = 0; ci < 2; ci++) {
            int col = n0 + wcol + nt * 8 + tg * 2 + ci;
            if (scalemode == 1) {
                float p  = pds[col & (HD - 1)];
                float sp = (p > 15.f) ? p : log1pf(expf(p));
                sc[nt][ci] = Q_SCALE_F * sp;
            } else {
                sc[nt][ci] = cscale;
            }
        }
    }
#pragma unroll
    for (int mt = 0; mt < 4; mt++) {
#pragma unroll
        for (int hf = 0; hf < 2; hf++) {
            int row = m0 + wrow + mt * 16 + hf * 8 + g;
#pragma unroll
            for (int nt = 0; nt < 4; nt++) {
                float vx = acc[mt][nt][hf * 2 + 0] * sc[nt][0];
                float vy = acc[mt][nt][hf * 2 + 1] * sc[nt][1];
                size_t off = (size_t)row * HS + n0 + wcol + nt * 8 + tg * 2;
                if (outHalf) {
                    *(__half2*)((__half*)Cv + off) = __floats2half2_rn(vx, vy);
                } else {
                    float2 v; v.x = vx; v.y = vy;
                    *(float2*)((float*)Cv + off) = v;
                }
            }
        }
    }
}

// relk: full-K per column, no atomics, writes half directly.
// 8 blocks (z==3, y==0, x 0..7): col = x*128 + (t&127); 2-way k-split in smem.
__device__ __forceinline__ void relk_body(
    const float* __restrict__ pe, const float* __restrict__ Wrel)
{
    float* spe = (float*)dynpool;              // [25][1024] = 102400 B
    const int t = threadIdx.x;                 // 256
    const int col = blockIdx.x * 128 + (t & 127);
    const int kh  = (t >> 7) * 512;

    for (int f = t; f < PQ * HS; f += 256)
        spe[f] = pe[f];
    __syncthreads();

    float acc[PQ];
#pragma unroll
    for (int p = 0; p < PQ; p++) acc[p] = 0.f;
    for (int kk = 0; kk < 512; kk++) {
        float w = Wrel[(size_t)(kh + kk) * HS + col];
#pragma unroll
        for (int p = 0; p < PQ; p++)
            acc[p] = fmaf(spe[p * HS + kh + kk], w, acc[p]);
    }
    __syncthreads();
    float* red = spe;                          // reuse: [256][25]
#pragma unroll
    for (int p = 0; p < PQ; p++) red[t * PQ + p] = acc[p];
    __syncthreads();
    if (t < 128) {
#pragma unroll
        for (int p = 0; p < PQ; p++) {
            float s = red[t * PQ + p] + red[(t + 128) * PQ + p];
            g_relkh[p * HS + col] = __float2half(s);
        }
    }
}

__global__ __launch_bounds__(256, 2) void qkv_gemm(
    const float* __restrict__ pds,
    const float* __restrict__ pe, const float* __restrict__ Wrel)
{
    int z = blockIdx.z;
    if (z == 3) {
        if (blockIdx.y == 0 && blockIdx.x < 8) relk_body(pe, Wrel);
        return;
    }
    if (z == 0)      gemm_fp16(g_xh, g_wth[0], g_qh, 1, 1, pds,  1.f);
    else if (z == 1) gemm_fp16(g_xh, g_wth[1], g_kh, 1, 0, 0, K_SCALE_F);
    else             gemm_fp16(g_xh, g_wth[2], g_vh, 1, 0, 0, 1.f);
}

__global__ __launch_bounds__(256, 2) void post_gemm(float* __restrict__ out)
{
    gemm_fp16(g_aoh, g_wth[3], out, 0, 0, 0, 1.f);
}

// ------ attention: quad of 4 chunks per CTA; 2 pair-parallel warp groups --
#define QPITCH 136
#define KPITCH 136
#define PPITCH 40
#define AT_SLOG 0                          // float [2][512]
#define AT_SBD  4096                       // float [2][512]
#define AT_QS   8192                       // half 64 x QPITCH
#define AT_KS   (AT_QS + 64*QPITCH*2)      // half 60 x KPITCH
#define AT_VS   (AT_KS + 60*KPITCH*2)      // half 68 x KPITCH
#define AT_RS   (AT_VS + 68*KPITCH*2)      // half 32 x KPITCH
#define AT_PS   (AT_RS + 32*KPITCH*2)      // half [2][16][PPITCH]
#define ATTN_SMEM (AT_PS + 2*16*PPITCH*2)  // 71680

__global__ __launch_bounds__(256) void attn_kernel()
{
    float*  slog = (float*)(dynpool + AT_SLOG);
    float*  sbd  = (float*)(dynpool + AT_SBD);
    __half* qs   = (__half*)(dynpool + AT_QS);
    __half* ks   = (__half*)(dynpool + AT_KS);
    __half* vs   = (__half*)(dynpool + AT_VS);
    __half* rs   = (__half*)(dynpool + AT_RS);
    __half* ps   = (__half*)(dynpool + AT_PS);

    const int bid = blockIdx.x;
    const int h  = bid & 7;
    const int q4 = (bid >> 3) % NQUAD;
    const int b  = bid / (8 * NQUAD);
    const int t  = threadIdx.x;
    const int lane = t & 31;
    const int warp = t >> 5;
    const int wr = warp & 3;
    const int wg = warp >> 2;
    const int lt = t & 127;
    const int g  = lane >> 2;
    const int tg = lane & 3;

    const size_t base = (size_t)b * SEQ * HS + (size_t)h * HD;
    const int r0g = q4 * 48;
    const int s0  = r0g - PASTQ;

    for (int f = t; f < 48 * 16; f += 256) {
        int i = f >> 4, c = (f & 15) << 3;
        int chunk = i / 12, r = i - chunk * 12;
        *(int4*)&qs[(chunk * 16 + r) * QPITCH + c] =
            *(const int4*)&g_qh[base + (size_t)(r0g + i) * HS + c];
    }
    for (int f = t; f < 60 * 16; f += 256) {
        int j = f >> 4, c = (f & 15) << 3;
        int s = s0 + j;
        int4 kv = make_int4(0, 0, 0, 0);
        int4 vv = make_int4(0, 0, 0, 0);
        if (s >= 0) {
            kv = *(const int4*)&g_kh[base + (size_t)s * HS + c];
            vv = *(const int4*)&g_vh[base + (size_t)s * HS + c];
        }
        *(int4*)&ks[j * KPITCH + c] = kv;
        *(int4*)&vs[j * KPITCH + c] = vv;
    }
    {
        int4* v4 = (int4*)(vs + 60 * KPITCH);
        int4 z = make_int4(0, 0, 0, 0);
        for (int f = t; f < 8 * KPITCH / 8; f += 256) v4[f] = z;
    }
    for (int f = t; f < PQ * 16; f += 256) {
        int pp = f >> 4, c = (f & 15) << 3;
        *(int4*)&rs[pp * KPITCH + c] =
            *(const int4*)&g_relkh[(size_t)pp * HS + (size_t)h * HD + c];
    }
    __syncthreads();

    const int aRow = (lane & 7) + ((lane >> 3) & 1) * 8;
    const int aCol = ((lane >> 4) & 1) * 8;
    const int bR   = lane & 7;
    const int bSel = ((lane >> 3) & 1) * 8;
    const int vr   = lane & 15;
    const int barid = 1 + wg;

    float*  slogp = slog + wg * 512;
    float*  sbdp  = sbd  + wg * 512;
    __half* psp   = ps   + wg * 16 * PPITCH;

#pragma unroll
    for (int cl = 0; cl < 2; cl++) {
        const int ci = 2 * wg + cl;
        const __half* qb = qs + ci * 16 * QPITCH;
        const __half* kb = ks + ci * 12 * KPITCH;
        const __half* vb = vs + ci * 12 * KPITCH;

        // scores
        {
            float cac[4] = {0.f, 0.f, 0.f, 0.f};
            float cbd[4] = {0.f, 0.f, 0.f, 0.f};
#pragma unroll
            for (int kh = 0; kh < HD; kh += 16) {
                unsigned a0, a1, a2, a3;
                ldm_x4(a0, a1, a2, a3, cvta_smem(&qb[aRow * QPITCH + kh + aCol]));
                unsigned r0, r1;
                ldm_x2(r0, r1, cvta_smem(&rs[(8 * wr + bR) * KPITCH + kh + bSel]));
                mma16816(cbd, a0, a1, a2, a3, r0, r1);
                if (wr < 3) {
                    unsigned k0, k1;
                    ldm_x2(k0, k1, cvta_smem(&kb[(8 * wr + bR) * KPITCH + kh + bSel]));
                    mma16816(cac, a0, a1, a2, a3, k0, k1);
                }
            }
            int c0 = 8 * wr + 2 * tg;
            if (wr < 3) {
                slogp[g * 32 + c0]           = cac[0];
                slogp[g * 32 + c0 + 1]       = cac[1];
                slogp[(g + 8) * 32 + c0]     = cac[2];
                slogp[(g + 8) * 32 + c0 + 1] = cac[3];
            }
            sbdp[g * 32 + c0]           = cbd[0];
            sbdp[g * 32 + c0 + 1]       = cbd[1];
            sbdp[(g + 8) * 32 + c0]     = cbd[2];
            sbdp[(g + 8) * 32 + c0 + 1] = cbd[3];
        }
        BARS(barid);

        // fused rel-shift + softcap + softmax (one row per thread, lt<12)
        if (lt < CHUNKQ) {
            float e_[CTXQ];
            float m = -1e30f;
#pragma unroll
            for (int j = 0; j < CTXQ; j++) {
                int e = lt * 24 + j;
                float val = slogp[lt * 32 + j] + sbdp[(e / PQ) * 32 + (e % PQ)];
                val = tanhf(val * (1.0f / 50.0f)) * 50.0f;
                e_[j] = val;
                m = fmaxf(m, val);
            }
            float s = 0.f;
#pragma unroll
            for (int j = 0; j < CTXQ; j++) {
                e_[j] = __expf(e_[j] - m);
                s += e_[j];
            }
            float inv = 1.0f / s;
#pragma unroll
            for (int j = 0; j < CTXQ; j += 2)
                *(__half2*)&psp[lt * PPITCH + j] =
                    __floats2half2_rn(e_[j] * inv, e_[j + 1] * inv);
            __half2 hz = __floats2half2_rn(0.f, 0.f);
#pragma unroll
            for (int j = CTXQ; j < 32; j += 2)
                *(__half2*)&psp[lt * PPITCH + j] = hz;
        }
        BARS(barid);

        // out = P @ V
        {
            unsigned qa[8];
            ldm_x4(qa[0], qa[1], qa[2], qa[3],
                   cvta_smem(&psp[aRow * PPITCH + aCol]));
            ldm_x4(qa[4], qa[5], qa[6], qa[7],
                   cvta_smem(&psp[aRow * PPITCH + 16 + aCol]));
#pragma unroll
            for (int nt = 0; nt < 4; nt++) {
                int n0 = 32 * wr + 8 * nt;
                float co[4] = {0.f, 0.f, 0.f, 0.f};
                unsigned v0, v1;
                ldm_x2_trans(v0, v1, cvta_smem(&vb[vr * KPITCH + n0]));
                mma16816(co, qa[0], qa[1], qa[2], qa[3], v0, v1);
                ldm_x2_trans(v0, v1, cvta_smem(&vb[(16 + vr) * KPITCH + n0]));
                mma16816(co, qa[4], qa[5], qa[6], qa[7], v0, v1);

                int d0 = n0 + 2 * tg;
                int row0 = r0g + ci * 12 + g;
                *(__half2*)&g_aoh[base + (size_t)row0 * HS + d0] =
                    __floats2half2_rn(co[0], co[1]);
                if (g < 4)
                    *(__half2*)&g_aoh[base + (size_t)(row0 + 8) * HS + d0] =
                        __floats2half2_rn(co[2], co[3]);
            }
        }
    }
}

// ---------------- launch ----------------
extern "C" void kernel_launch(void* const* d_in, const int* in_sizes, int n_in,
                              void* d_out, int out_size)
{
    const float* x     = (const float*)d_in[0];
    const float* pe    = (const float*)d_in[1];
    const float* Wq    = (const float*)d_in[2];
    const float* Wk    = (const float*)d_in[3];
    const float* Wv    = (const float*)d_in[4];
    const float* Wpost = (const float*)d_in[5];
    const float* Wrel  = (const float*)d_in[6];
    const float* pds   = (const float*)d_in[7];
    float* out = (float*)d_out;

    static int configured = 0;
    if (!configured) {
        cudaFuncSetAttribute(qkv_gemm,
            cudaFuncAttributeMaxDynamicSharedMemorySize, SMEM_DYN);
        cudaFuncSetAttribute(post_gemm,
            cudaFuncAttributeMaxDynamicSharedMemorySize, SMEM_DYN);
        cudaFuncSetAttribute(attn_kernel,
            cudaFuncAttributeMaxDynamicSharedMemorySize, ATTN_SMEM);
        configured = 1;
    }

    prep_all<<<XBLOCKS + 4096, 256>>>(x, Wq, Wk, Wv, Wpost);

    dim3 gq(HS / BN, MROWS / BM, 4);
    qkv_gemm<<<gq, 256, SMEM_DYN>>>(pds, pe, Wrel);

    attn_kernel<<<BATCH * NQUAD * NH, 256, ATTN_SMEM>>>();

    dim3 gp(HS / BN, MROWS / BM);
    post_gemm<<<gp, 256, SMEM_DYN>>>(out);
}

// round 15
// speedup vs baseline: 1.1639x; 1.1639x over previous
#include <cuda_runtime.h>
#include <cuda_fp16.h>
#include <math.h>

// ---------------- problem constants ----------------
#define HS    1024
#define NH    8
#define HD    128
#define BATCH 16
#define SEQ   2400
#define NBLK  200
#define NQUAD 50
#define MROWS (BATCH*SEQ)          // 38400

#define CHUNKQ 12
#define PASTQ  12
#define CTXQ   24
#define PQ     25

#define Q_SCALE_F (0.08838834764831845f / 0.6931471805599453f)
#define K_SCALE_F (1.3132616875182228f / 0.6931471805599453f)

// ---------------- scratch ----------------
__device__ __half g_qh [(size_t)MROWS * HS];
__device__ __half g_kh [(size_t)MROWS * HS];
__device__ __half g_vh [(size_t)MROWS * HS];
__device__ __half g_aoh[(size_t)MROWS * HS];
__device__ __half g_xh [(size_t)MROWS * HS];
__device__ __half g_wth[4][(size_t)HS * HS];
__device__ float  g_relk [PQ * HS];
__device__ __half g_relkh[PQ * HS];

__device__ __forceinline__ unsigned cvta_smem(const void* p) {
    return (unsigned)__cvta_generic_to_shared(p);
}
__device__ __forceinline__ void cp_async16(void* dst, const void* src) {
    asm volatile("cp.async.cg.shared.global [%0], [%1], 16;\n"
                 :: "r"(cvta_smem(dst)), "l"(src));
}
__device__ __forceinline__ void cp_commit() {
    asm volatile("cp.async.commit_group;\n");
}
__device__ __forceinline__ void ldm_x4(unsigned& r0, unsigned& r1,
                                       unsigned& r2, unsigned& r3, unsigned a) {
    asm volatile("ldmatrix.sync.aligned.m8n8.x4.shared.b16 {%0,%1,%2,%3}, [%4];\n"
                 : "=r"(r0), "=r"(r1), "=r"(r2), "=r"(r3) : "r"(a));
}
__device__ __forceinline__ void ldm_x2(unsigned& r0, unsigned& r1, unsigned a) {
    asm volatile("ldmatrix.sync.aligned.m8n8.x2.shared.b16 {%0,%1}, [%2];\n"
                 : "=r"(r0), "=r"(r1) : "r"(a));
}
__device__ __forceinline__ void ldm_x2_trans(unsigned& r0, unsigned& r1, unsigned a) {
    asm volatile("ldmatrix.sync.aligned.m8n8.x2.trans.shared.b16 {%0,%1}, [%2];\n"
                 : "=r"(r0), "=r"(r1) : "r"(a));
}
__device__ __forceinline__ void mma16816(float* d, unsigned a0, unsigned a1,
                                         unsigned a2, unsigned a3,
                                         unsigned b0, unsigned b1) {
    asm volatile(
        "mma.sync.aligned.m16n8k16.row.col.f32.f16.f16.f32 "
        "{%0,%1,%2,%3}, {%4,%5,%6,%7}, {%8,%9}, {%0,%1,%2,%3};\n"
        : "+f"(d[0]), "+f"(d[1]), "+f"(d[2]), "+f"(d[3])
        : "r"(a0), "r"(a1), "r"(a2), "r"(a3), "r"(b0), "r"(b1));
}
#define BARS(id) asm volatile("bar.sync %0, %1;" :: "r"(id), "r"(128) : "memory")

// ---------------- prep ----------------
__global__ __launch_bounds__(256) void prep_xh(const float* __restrict__ x)
{
    if (blockIdx.x < 100) g_relk[blockIdx.x * 256 + threadIdx.x] = 0.f;
    size_t i = ((size_t)blockIdx.x * 256 + threadIdx.x) * 4;
    float4 v = *(const float4*)(x + i);
    *(__half2*)(g_xh + i)     = __floats2half2_rn(v.x, v.y);
    *(__half2*)(g_xh + i + 2) = __floats2half2_rn(v.z, v.w);
}

__global__ __launch_bounds__(256) void prep_wh(
    const float* __restrict__ Wq, const float* __restrict__ Wk,
    const float* __restrict__ Wv, const float* __restrict__ Wpost)
{
    __shared__ float tile[32][33];
    const float* src = (blockIdx.z == 0) ? Wq : (blockIdx.z == 1) ? Wk
                     : (blockIdx.z == 2) ? Wv : Wpost;
    const int tx = threadIdx.x, ty = threadIdx.y;
    const int x0 = blockIdx.x * 32, y0 = blockIdx.y * 32;
#pragma unroll
    for (int i = 0; i < 32; i += 8)
        tile[ty + i][tx] = src[(size_t)(y0 + ty + i) * HS + x0 + tx];
    __syncthreads();
    __half* dst = g_wth[blockIdx.z];
#pragma unroll
    for (int i = 0; i < 32; i += 8)
        dst[(size_t)(x0 + ty + i) * HS + y0 + tx] = __float2half(tile[tx][ty + i]);
}

__global__ __launch_bounds__(256) void relk_half()
{
    int i = blockIdx.x * 256 + threadIdx.x;
    g_relkh[i] = __float2half(g_relk[i]);
}

// ------------ fp16 tensor-core GEMM: 128x128, BK=64, 3-stage ring ---------
#define BM 128
#define BN 128
#define BKH 64
#define BKP 72
#define KTILES (HS / BKH)                 // 16
#define NSTAGE 3
#define OP_ST (BM * BKP)
#define STG   (2 * OP_ST)
#define SMEM_DYN (NSTAGE * STG * 2)       // 110592 bytes

extern __shared__ __align__(16) unsigned char dynpool[];

__device__ __forceinline__ void gemm_fill(
    __half* base, int slot, int ktile, int t,
    const __half* __restrict__ Abase, const __half* __restrict__ Bbase)
{
    const __half* Ap = Abase + ktile * BKH;
    const __half* Bp = Bbase + ktile * BKH;
    __half* Ad = base + slot * STG;
    __half* Bd = Ad + OP_ST;
#pragma unroll
    for (int i = 0; i < 4; i++) {
        int q = t + i * 256;
        int row = q >> 3, c = (q & 7) * 8;
        cp_async16(Ad + (size_t)row * BKP + c, Ap + (size_t)row * HS + c);
        cp_async16(Bd + (size_t)row * BKP + c, Bp + (size_t)row * HS + c);
    }
    cp_commit();
}

__device__ __forceinline__ void gemm_fp16(
    const __half* __restrict__ A, const __half* __restrict__ Wt,
    void* __restrict__ Cv, int outHalf,
    int scalemode, const float* __restrict__ pds, float cscale)
{
    __half* Sb = (__half*)dynpool;

    const int t    = threadIdx.x;
    const int lane = t & 31;
    const int warp = t >> 5;
    const int wrow = (warp & 1) * 64;
    const int wcol = (warp >> 1) * 32;
    const int g    = lane >> 2;
    const int tg   = lane & 3;

    const int m0 = blockIdx.y * BM;
    const int n0 = blockIdx.x * BN;

    const __half* Abase = A  + (size_t)m0 * HS;
    const __half* Bbase = Wt + (size_t)n0 * HS;

    const int aRow = (lane & 7) + ((lane >> 3) & 1) * 8;
    const int aCol = ((lane >> 4) & 1) * 8;
    const int bRow = (lane & 7) + ((lane >> 4) & 1) * 8;
    const int bCol = ((lane >> 3) & 1) * 8;

    float acc[4][4][4];
#pragma unroll
    for (int i = 0; i < 4; i++)
#pragma unroll
        for (int j = 0; j < 4; j++)
#pragma unroll
            for (int c = 0; c < 4; c++) acc[i][j][c] = 0.f;

    gemm_fill(Sb, 0, 0, t, Abase, Bbase);
    gemm_fill(Sb, 1, 1, t, Abase, Bbase);

    for (int tile = 0; tile < KTILES; ++tile) {
        if (tile < KTILES - 1) asm volatile("cp.async.wait_group 1;\n");
        else                   asm volatile("cp.async.wait_group 0;\n");
        __syncthreads();

        if (tile + 2 < KTILES)
            gemm_fill(Sb, (tile + 2) % NSTAGE, tile + 2, t, Abase, Bbase);

        const int bo = (tile % NSTAGE) * STG;
        __half* As = Sb + bo;
        __half* Bs = As + OP_ST;
#pragma unroll
        for (int kk = 0; kk < 4; kk++) {
            const int kh = kk * 16;
            unsigned af[4][4], bf[4][2];
#pragma unroll
            for (int mt = 0; mt < 4; mt++) {
                unsigned a = cvta_smem(As +
                    (size_t)(wrow + mt * 16 + aRow) * BKP + kh + aCol);
                ldm_x4(af[mt][0], af[mt][1], af[mt][2], af[mt][3], a);
            }
#pragma unroll
            for (int p = 0; p < 2; p++) {
                unsigned a = cvta_smem(Bs +
                    (size_t)(wcol + p * 16 + bRow) * BKP + kh + bCol);
                ldm_x4(bf[2*p][0], bf[2*p][1], bf[2*p+1][0], bf[2*p+1][1], a);
            }
#pragma unroll
            for (int mt = 0; mt < 4; mt++)
#pragma unroll
                for (int nt = 0; nt < 4; nt++)
                    mma16816(acc[mt][nt], af[mt][0], af[mt][1], af[mt][2],
                             af[mt][3], bf[nt][0], bf[nt][1]);
        }
    }

    float sc[4][2];
#pragma unroll
    for (int nt = 0; nt < 4; nt++) {
#pragma unroll
        for (int ci = 0; ci < 2; ci++) {
            int col = n0 + wcol + nt * 8 + tg * 2 + ci;
            if (scalemode == 1) {
                float p  = pds[col & (HD - 1)];
                float sp = (p > 15.f) ? p : log1pf(expf(p));
                sc[nt][ci] = Q_SCALE_F * sp;
            } else {
                sc[nt][ci] = cscale;
            }
        }
    }
#pragma unroll
    for (int mt = 0; mt < 4; mt++) {
#pragma unroll
        for (int hf = 0; hf < 2; hf++) {
            int row = m0 + wrow + mt * 16 + hf * 8 + g;
#pragma unroll
            for (int nt = 0; nt < 4; nt++) {
                float vx = acc[mt][nt][hf * 2 + 0] * sc[nt][0];
                float vy = acc[mt][nt][hf * 2 + 1] * sc[nt][1];
                size_t off = (size_t)row * HS + n0 + wcol + nt * 8 + tg * 2;
                if (outHalf) {
                    *(__half2*)((__half*)Cv + off) = __floats2half2_rn(vx, vy);
                } else {
                    float2 v; v.x = vx; v.y = vy;
                    *(float2*)((float*)Cv + off) = v;
                }
            }
        }
    }
}

// relk partial (z==3 slice of qkv_gemm; 256 threads, 32 blocks, k-split)
__device__ __forceinline__ void relk_body(
    const float* __restrict__ pe, const float* __restrict__ Wrel)
{
    float* spe = (float*)dynpool;
    const int t = threadIdx.x;
    const int col = blockIdx.x * 128 + (t & 127);
    const int k0  = blockIdx.y * 256;
    const int kh  = (t >> 7) * 128;

    for (int f = t; f < PQ * 256; f += 256)
        spe[f] = pe[(f >> 8) * HS + k0 + (f & 255)];
    __syncthreads();

    float acc[PQ];
#pragma unroll
    for (int p = 0; p < PQ; p++) acc[p] = 0.f;
    for (int kk = 0; kk < 128; kk++) {
        float w = Wrel[(size_t)(k0 + kh + kk) * HS + col];
#pragma unroll
        for (int p = 0; p < PQ; p++) acc[p] = fmaf(spe[p * 256 + kh + kk], w, acc[p]);
    }
#pragma unroll
    for (int p = 0; p < PQ; p++) atomicAdd(&g_relk[p * HS + col], acc[p]);
}

__global__ __launch_bounds__(256, 2) void qkv_gemm(
    const float* __restrict__ pds,
    const float* __restrict__ pe, const float* __restrict__ Wrel)
{
    int z = blockIdx.z;
    if (z == 3) {
        if (blockIdx.y < 4 && blockIdx.x < 8) relk_body(pe, Wrel);
        return;
    }
    if (z == 0)      gemm_fp16(g_xh, g_wth[0], g_qh, 1, 1, pds,  1.f);
    else if (z == 1) gemm_fp16(g_xh, g_wth[1], g_kh, 1, 0, 0, K_SCALE_F);
    else             gemm_fp16(g_xh, g_wth[2], g_vh, 1, 0, 0, 1.f);
}

__global__ __launch_bounds__(256, 2) void post_gemm(float* __restrict__ out)
{
    gemm_fp16(g_aoh, g_wth[3], out, 0, 0, 0, 1.f);
}

// ------ attention: quad of 4 chunks per CTA; 2 pair-parallel warp groups --
#define QPITCH 136
#define KPITCH 136
#define PPITCH 40
#define AT_SLOG 0                          // float [2][512]
#define AT_SBD  4096                       // float [2][512]
#define AT_QS   8192                       // half 64 x QPITCH
#define AT_KS   (AT_QS + 64*QPITCH*2)      // half 60 x KPITCH
#define AT_VS   (AT_KS + 60*KPITCH*2)      // half 68 x KPITCH
#define AT_RS   (AT_VS + 68*KPITCH*2)      // half 32 x KPITCH
#define AT_PS   (AT_RS + 32*KPITCH*2)      // half [2][16][PPITCH]
#define ATTN_SMEM (AT_PS + 2*16*PPITCH*2)  // 71680

__global__ __launch_bounds__(256) void attn_kernel()
{
    float*  slog = (float*)(dynpool + AT_SLOG);
    float*  sbd  = (float*)(dynpool + AT_SBD);
    __half* qs   = (__half*)(dynpool + AT_QS);
    __half* ks   = (__half*)(dynpool + AT_KS);
    __half* vs   = (__half*)(dynpool + AT_VS);
    __half* rs   = (__half*)(dynpool + AT_RS);
    __half* ps   = (__half*)(dynpool + AT_PS);

    const int bid = blockIdx.x;
    const int h  = bid & 7;
    const int q4 = (bid >> 3) % NQUAD;
    const int b  = bid / (8 * NQUAD);
    const int t  = threadIdx.x;
    const int lane = t & 31;
    const int warp = t >> 5;
    const int wr = warp & 3;
    const int wg = warp >> 2;
    const int lt = t & 127;
    const int g  = lane >> 2;
    const int tg = lane & 3;

    const size_t base = (size_t)b * SEQ * HS + (size_t)h * HD;
    const int r0g = q4 * 48;
    const int s0  = r0g - PASTQ;

    for (int f = t; f < 48 * 16; f += 256) {
        int i = f >> 4, c = (f & 15) << 3;
        int chunk = i / 12, r = i - chunk * 12;
        *(int4*)&qs[(chunk * 16 + r) * QPITCH + c] =
            *(const int4*)&g_qh[base + (size_t)(r0g + i) * HS + c];
    }
    for (int f = t; f < 60 * 16; f += 256) {
        int j = f >> 4, c = (f & 15) << 3;
        int s = s0 + j;
        int4 kv = make_int4(0, 0, 0, 0);
        int4 vv = make_int4(0, 0, 0, 0);
        if (s >= 0) {
            kv = *(const int4*)&g_kh[base + (size_t)s * HS + c];
            vv = *(const int4*)&g_vh[base + (size_t)s * HS + c];
        }
        *(int4*)&ks[j * KPITCH + c] = kv;
        *(int4*)&vs[j * KPITCH + c] = vv;
    }
    {
        int4* v4 = (int4*)(vs + 60 * KPITCH);
        int4 z = make_int4(0, 0, 0, 0);
        for (int f = t; f < 8 * KPITCH / 8; f += 256) v4[f] = z;
    }
    for (int f = t; f < PQ * 16; f += 256) {
        int pp = f >> 4, c = (f & 15) << 3;
        *(int4*)&rs[pp * KPITCH + c] =
            *(const int4*)&g_relkh[(size_t)pp * HS + (size_t)h * HD + c];
    }
    __syncthreads();

    const int aRow = (lane & 7) + ((lane >> 3) & 1) * 8;
    const int aCol = ((lane >> 4) & 1) * 8;
    const int bR   = lane & 7;
    const int bSel = ((lane >> 3) & 1) * 8;
    const int vr   = lane & 15;
    const int barid = 1 + wg;

    float*  slogp = slog + wg * 512;
    float*  sbdp  = sbd  + wg * 512;
    __half* psp   = ps   + wg * 16 * PPITCH;

#pragma unroll
    for (int cl = 0; cl < 2; cl++) {
        const int ci = 2 * wg + cl;
        const __half* qb = qs + ci * 16 * QPITCH;
        const __half* kb = ks + ci * 12 * KPITCH;
        const __half* vb = vs + ci * 12 * KPITCH;

        // scores
        {
            float cac[4] = {0.f, 0.f, 0.f, 0.f};
            float cbd[4] = {0.f, 0.f, 0.f, 0.f};
#pragma unroll
            for (int kh = 0; kh < HD; kh += 16) {
                unsigned a0, a1, a2, a3;
                ldm_x4(a0, a1, a2, a3, cvta_smem(&qb[aRow * QPITCH + kh + aCol]));
                unsigned r0, r1;
                ldm_x2(r0, r1, cvta_smem(&rs[(8 * wr + bR) * KPITCH + kh + bSel]));
                mma16816(cbd, a0, a1, a2, a3, r0, r1);
                if (wr < 3) {
                    unsigned k0, k1;
                    ldm_x2(k0, k1, cvta_smem(&kb[(8 * wr + bR) * KPITCH + kh + bSel]));
                    mma16816(cac, a0, a1, a2, a3, k0, k1);
                }
            }
            int c0 = 8 * wr + 2 * tg;
            if (wr < 3) {
                slogp[g * 32 + c0]           = cac[0];
                slogp[g * 32 + c0 + 1]       = cac[1];
                slogp[(g + 8) * 32 + c0]     = cac[2];
                slogp[(g + 8) * 32 + c0 + 1] = cac[3];
            }
            sbdp[g * 32 + c0]           = cbd[0];
            sbdp[g * 32 + c0 + 1]       = cbd[1];
            sbdp[(g + 8) * 32 + c0]     = cbd[2];
            sbdp[(g + 8) * 32 + c0 + 1] = cbd[3];
        }
        BARS(barid);

        // fused rel-shift + softcap + softmax (one row per thread, lt<12)
        if (lt < CHUNKQ) {
            float e_[CTXQ];
            float m = -1e30f;
#pragma unroll
            for (int j = 0; j < CTXQ; j++) {
                int e = lt * 24 + j;
                float val = slogp[lt * 32 + j] + sbdp[(e / PQ) * 32 + (e % PQ)];
                val = tanhf(val * (1.0f / 50.0f)) * 50.0f;
                e_[j] = val;
                m = fmaxf(m, val);
            }
            float s = 0.f;
#pragma unroll
            for (int j = 0; j < CTXQ; j++) {
                e_[j] = __expf(e_[j] - m);
                s += e_[j];
            }
            float inv = 1.0f / s;
#pragma unroll
            for (int j = 0; j < CTXQ; j += 2)
                *(__half2*)&psp[lt * PPITCH + j] =
                    __floats2half2_rn(e_[j] * inv, e_[j + 1] * inv);
            __half2 hz = __floats2half2_rn(0.f, 0.f);
#pragma unroll
            for (int j = CTXQ; j < 32; j += 2)
                *(__half2*)&psp[lt * PPITCH + j] = hz;
        }
        BARS(barid);

        // out = P @ V
        {
            unsigned qa[8];
            ldm_x4(qa[0], qa[1], qa[2], qa[3],
                   cvta_smem(&psp[aRow * PPITCH + aCol]));
            ldm_x4(qa[4], qa[5], qa[6], qa[7],
                   cvta_smem(&psp[aRow * PPITCH + 16 + aCol]));
#pragma unroll
            for (int nt = 0; nt < 4; nt++) {
                int n0 = 32 * wr + 8 * nt;
                float co[4] = {0.f, 0.f, 0.f, 0.f};
                unsigned v0, v1;
                ldm_x2_trans(v0, v1, cvta_smem(&vb[vr * KPITCH + n0]));
                mma16816(co, qa[0], qa[1], qa[2], qa[3], v0, v1);
                ldm_x2_trans(v0, v1, cvta_smem(&vb[(16 + vr) * KPITCH + n0]));
                mma16816(co, qa[4], qa[5], qa[6], qa[7], v0, v1);

                int d0 = n0 + 2 * tg;
                int row0 = r0g + ci * 12 + g;
                *(__half2*)&g_aoh[base + (size_t)row0 * HS + d0] =
                    __floats2half2_rn(co[0], co[1]);
                if (g < 4)
                    *(__half2*)&g_aoh[base + (size_t)(row0 + 8) * HS + d0] =
                        __floats2half2_rn(co[2], co[3]);
            }
        }
    }
}

// ---------------- launch ----------------
extern "C" void kernel_launch(void* const* d_in, const int* in_sizes, int n_in,
                              void* d_out, int out_size)
{
    const float* x     = (const float*)d_in[0];
    const float* pe    = (const float*)d_in[1];
    const float* Wq    = (const float*)d_in[2];
    const float* Wk    = (const float*)d_in[3];
    const float* Wv    = (const float*)d_in[4];
    const float* Wpost = (const float*)d_in[5];
    const float* Wrel  = (const float*)d_in[6];
    const float* pds   = (const float*)d_in[7];
    float* out = (float*)d_out;

    static int configured = 0;
    if (!configured) {
        cudaFuncSetAttribute(qkv_gemm,
            cudaFuncAttributeMaxDynamicSharedMemorySize, SMEM_DYN);
        cudaFuncSetAttribute(post_gemm,
            cudaFuncAttributeMaxDynamicSharedMemorySize, SMEM_DYN);
        cudaFuncSetAttribute(attn_kernel,
            cudaFuncAttributeMaxDynamicSharedMemorySize, ATTN_SMEM);
        configured = 1;
    }

    prep_xh<<<(size_t)MROWS * HS / 4 / 256, 256>>>(x);
    prep_wh<<<dim3(32, 32, 4), dim3(32, 8)>>>(Wq, Wk, Wv, Wpost);

    dim3 gq(HS / BN, MROWS / BM, 4);
    qkv_gemm<<<gq, 256, SMEM_DYN>>>(pds, pe, Wrel);

    relk_half<<<PQ * HS / 256, 256>>>();

    attn_kernel<<<BATCH * NQUAD * NH, 256, ATTN_SMEM>>>();

    dim3 gp(HS / BN, MROWS / BM);
    post_gemm<<<gp, 256, SMEM_DYN>>>(out);
}

// round 16
// speedup vs baseline: 1.1762x; 1.0106x over previous
#include <cuda_runtime.h>
#include <cuda_fp16.h>
#include <math.h>

// ---------------- problem constants ----------------
#define HS    1024
#define NH    8
#define HD    128
#define BATCH 16
#define SEQ   2400
#define NBLK  200
#define NQUAD 50
#define MROWS (BATCH*SEQ)          // 38400

#define CHUNKQ 12
#define PASTQ  12
#define CTXQ   24
#define PQ     25

#define Q_SCALE_F (0.08838834764831845f / 0.6931471805599453f)
#define K_SCALE_F (1.3132616875182228f / 0.6931471805599453f)

// ---------------- scratch ----------------
__device__ __half g_qh [(size_t)MROWS * HS];
__device__ __half g_kh [(size_t)MROWS * HS];
__device__ __half g_vh [(size_t)MROWS * HS];
__device__ __half g_aoh[(size_t)MROWS * HS];
__device__ __half g_xh [(size_t)MROWS * HS];
__device__ __half g_wth[4][(size_t)HS * HS];
__device__ float  g_relk [PQ * HS];
__device__ __half g_relkh[PQ * HS];

__device__ __forceinline__ unsigned cvta_smem(const void* p) {
    return (unsigned)__cvta_generic_to_shared(p);
}
__device__ __forceinline__ void cp_async16(void* dst, const void* src) {
    asm volatile("cp.async.cg.shared.global [%0], [%1], 16;\n"
                 :: "r"(cvta_smem(dst)), "l"(src));
}
__device__ __forceinline__ void cp_commit() {
    asm volatile("cp.async.commit_group;\n");
}
__device__ __forceinline__ void ldm_x4(unsigned& r0, unsigned& r1,
                                       unsigned& r2, unsigned& r3, unsigned a) {
    asm volatile("ldmatrix.sync.aligned.m8n8.x4.shared.b16 {%0,%1,%2,%3}, [%4];\n"
                 : "=r"(r0), "=r"(r1), "=r"(r2), "=r"(r3) : "r"(a));
}
__device__ __forceinline__ void ldm_x2(unsigned& r0, unsigned& r1, unsigned a) {
    asm volatile("ldmatrix.sync.aligned.m8n8.x2.shared.b16 {%0,%1}, [%2];\n"
                 : "=r"(r0), "=r"(r1) : "r"(a));
}
__device__ __forceinline__ void ldm_x2_trans(unsigned& r0, unsigned& r1, unsigned a) {
    asm volatile("ldmatrix.sync.aligned.m8n8.x2.trans.shared.b16 {%0,%1}, [%2];\n"
                 : "=r"(r0), "=r"(r1) : "r"(a));
}
__device__ __forceinline__ void mma16816(float* d, unsigned a0, unsigned a1,
                                         unsigned a2, unsigned a3,
                                         unsigned b0, unsigned b1) {
    asm volatile(
        "mma.sync.aligned.m16n8k16.row.col.f32.f16.f16.f32 "
        "{%0,%1,%2,%3}, {%4,%5,%6,%7}, {%8,%9}, {%0,%1,%2,%3};\n"
        : "+f"(d[0]), "+f"(d[1]), "+f"(d[2]), "+f"(d[3])
        : "r"(a0), "r"(a1), "r"(a2), "r"(a3), "r"(b0), "r"(b1));
}
#define BARS(id) asm volatile("bar.sync %0, %1;" :: "r"(id), "r"(128) : "memory")

// ------ unified prep: x->half + relk zero (blocks < XBLOCKS), then W^T ----
#define XBLOCKS (MROWS * HS / 1024)      // 38400
__global__ __launch_bounds__(256) void prep_all(
    const float* __restrict__ x,
    const float* __restrict__ Wq, const float* __restrict__ Wk,
    const float* __restrict__ Wv, const float* __restrict__ Wpost)
{
    const int t = threadIdx.x;
    if (blockIdx.x < XBLOCKS) {
        if (blockIdx.x < 100) g_relk[blockIdx.x * 256 + t] = 0.f;
        size_t i = ((size_t)blockIdx.x * 256 + t) * 4;
        float4 v = *(const float4*)(x + i);
        *(__half2*)(g_xh + i)     = __floats2half2_rn(v.x, v.y);
        *(__half2*)(g_xh + i + 2) = __floats2half2_rn(v.z, v.w);
        return;
    }
    // W transpose: 4096 blocks, one 32x32 tile each
    __shared__ float tile[32][33];
    int bid2 = blockIdx.x - XBLOCKS;
    int w  = bid2 >> 10;
    int ti = bid2 & 1023;
    int bx = ti & 31, by = ti >> 5;
    const float* src = (w == 0) ? Wq : (w == 1) ? Wk : (w == 2) ? Wv : Wpost;
    const int tx = t & 31, ty = t >> 5;    // 32 x 8
    const int x0 = bx * 32, y0 = by * 32;
#pragma unroll
    for (int i = 0; i < 32; i += 8)
        tile[ty + i][tx] = src[(size_t)(y0 + ty + i) * HS + x0 + tx];
    __syncthreads();
    __half* dst = g_wth[w];
#pragma unroll
    for (int i = 0; i < 32; i += 8)
        dst[(size_t)(x0 + ty + i) * HS + y0 + tx] = __float2half(tile[tx][ty + i]);
}

__global__ __launch_bounds__(256) void relk_half()
{
    int i = blockIdx.x * 256 + threadIdx.x;
    g_relkh[i] = __float2half(g_relk[i]);
}

// ------------ fp16 tensor-core GEMM: 128x128, BK=64, 3-stage ring ---------
#define BM 128
#define BN 128
#define BKH 64
#define BKP 72
#define KTILES (HS / BKH)                 // 16
#define NSTAGE 3
#define OP_ST (BM * BKP)
#define STG   (2 * OP_ST)
#define SMEM_DYN (NSTAGE * STG * 2)       // 110592 bytes

extern __shared__ __align__(16) unsigned char dynpool[];

__device__ __forceinline__ void gemm_fill(
    __half* base, int slot, int ktile, int t,
    const __half* __restrict__ Abase, const __half* __restrict__ Bbase)
{
    const __half* Ap = Abase + ktile * BKH;
    const __half* Bp = Bbase + ktile * BKH;
    __half* Ad = base + slot * STG;
    __half* Bd = Ad + OP_ST;
#pragma unroll
    for (int i = 0; i < 4; i++) {
        int q = t + i * 256;
        int row = q >> 3, c = (q & 7) * 8;
        cp_async16(Ad + (size_t)row * BKP + c, Ap + (size_t)row * HS + c);
        cp_async16(Bd + (size_t)row * BKP + c, Bp + (size_t)row * HS + c);
    }
    cp_commit();
}

__device__ __forceinline__ void gemm_fp16(
    const __half* __restrict__ A, const __half* __restrict__ Wt,
    void* __restrict__ Cv, int outHalf,
    int scalemode, const float* __restrict__ pds, float cscale)
{
    __half* Sb = (__half*)dynpool;

    const int t    = threadIdx.x;
    const int lane = t & 31;
    const int warp = t >> 5;
    const int wrow = (warp & 1) * 64;
    const int wcol = (warp >> 1) * 32;
    const int g    = lane >> 2;
    const int tg   = lane & 3;

    const int m0 = blockIdx.y * BM;
    const int n0 = blockIdx.x * BN;

    const __half* Abase = A  + (size_t)m0 * HS;
    const __half* Bbase = Wt + (size_t)n0 * HS;

    const int aRow = (lane & 7) + ((lane >> 3) & 1) * 8;
    const int aCol = ((lane >> 4) & 1) * 8;
    const int bRow = (lane & 7) + ((lane >> 4) & 1) * 8;
    const int bCol = ((lane >> 3) & 1) * 8;

    float acc[4][4][4];
#pragma unroll
    for (int i = 0; i < 4; i++)
#pragma unroll
        for (int j = 0; j < 4; j++)
#pragma unroll
            for (int c = 0; c < 4; c++) acc[i][j][c] = 0.f;

    gemm_fill(Sb, 0, 0, t, Abase, Bbase);
    gemm_fill(Sb, 1, 1, t, Abase, Bbase);

    for (int tile = 0; tile < KTILES; ++tile) {
        if (tile < KTILES - 1) asm volatile("cp.async.wait_group 1;\n");
        else                   asm volatile("cp.async.wait_group 0;\n");
        __syncthreads();

        if (tile + 2 < KTILES)
            gemm_fill(Sb, (tile + 2) % NSTAGE, tile + 2, t, Abase, Bbase);

        const int bo = (tile % NSTAGE) * STG;
        __half* As = Sb + bo;
        __half* Bs = As + OP_ST;
#pragma unroll
        for (int kk = 0; kk < 4; kk++) {
            const int kh = kk * 16;
            unsigned af[4][4], bf[4][2];
#pragma unroll
            for (int mt = 0; mt < 4; mt++) {
                unsigned a = cvta_smem(As +
                    (size_t)(wrow + mt * 16 + aRow) * BKP + kh + aCol);
                ldm_x4(af[mt][0], af[mt][1], af[mt][2], af[mt][3], a);
            }
#pragma unroll
            for (int p = 0; p < 2; p++) {
                unsigned a = cvta_smem(Bs +
                    (size_t)(wcol + p * 16 + bRow) * BKP + kh + bCol);
                ldm_x4(bf[2*p][0], bf[2*p][1], bf[2*p+1][0], bf[2*p+1][1], a);
            }
#pragma unroll
            for (int mt = 0; mt < 4; mt++)
#pragma unroll
                for (int nt = 0; nt < 4; nt++)
                    mma16816(acc[mt][nt], af[mt][0], af[mt][1], af[mt][2],
                             af[mt][3], bf[nt][0], bf[nt][1]);
        }
    }

    float sc[4][2];
#pragma unroll
    for (int nt = 0; nt < 4; nt++) {
#pragma unroll
        for (int ci = 0; ci < 2; ci++) {
            int col = n0 + wcol + nt * 8 + tg * 2 + ci;
            if (scalemode == 1) {
                float p  = pds[col & (HD - 1)];
                float sp = (p > 15.f) ? p : log1pf(expf(p));
                sc[nt][ci] = Q_SCALE_F * sp;
            } else {
                sc[nt][ci] = cscale;
            }
        }
    }
#pragma unroll
    for (int mt = 0; mt < 4; mt++) {
#pragma unroll
        for (int hf = 0; hf < 2; hf++) {
            int row = m0 + wrow + mt * 16 + hf * 8 + g;
#pragma unroll
            for (int nt = 0; nt < 4; nt++) {
                float vx = acc[mt][nt][hf * 2 + 0] * sc[nt][0];
                float vy = acc[mt][nt][hf * 2 + 1] * sc[nt][1];
                size_t off = (size_t)row * HS + n0 + wcol + nt * 8 + tg * 2;
                if (outHalf) {
                    *(__half2*)((__half*)Cv + off) = __floats2half2_rn(vx, vy);
                } else {
                    float2 v; v.x = vx; v.y = vy;
                    *(float2*)((float*)Cv + off) = v;
                }
            }
        }
    }
}

// relk partial (z==3 slice of qkv_gemm; 256 threads, 32 blocks, k-split)
__device__ __forceinline__ void relk_body(
    const float* __restrict__ pe, const float* __restrict__ Wrel)
{
    float* spe = (float*)dynpool;
    const int t = threadIdx.x;
    const int col = blockIdx.x * 128 + (t & 127);
    const int k0  = blockIdx.y * 256;
    const int kh  = (t >> 7) * 128;

    for (int f = t; f < PQ * 256; f += 256)
        spe[f] = pe[(f >> 8) * HS + k0 + (f & 255)];
    __syncthreads();

    float acc[PQ];
#pragma unroll
    for (int p = 0; p < PQ; p++) acc[p] = 0.f;
    for (int kk = 0; kk < 128; kk++) {
        float w = Wrel[(size_t)(k0 + kh + kk) * HS + col];
#pragma unroll
        for (int p = 0; p < PQ; p++) acc[p] = fmaf(spe[p * 256 + kh + kk], w, acc[p]);
    }
#pragma unroll
    for (int p = 0; p < PQ; p++) atomicAdd(&g_relk[p * HS + col], acc[p]);
}

__global__ __launch_bounds__(256, 2) void qkv_gemm(
    const float* __restrict__ pds,
    const float* __restrict__ pe, const float* __restrict__ Wrel)
{
    int z = blockIdx.z;
    if (z == 3) {
        if (blockIdx.y < 4 && blockIdx.x < 8) relk_body(pe, Wrel);
        return;
    }
    if (z == 0)      gemm_fp16(g_xh, g_wth[0], g_qh, 1, 1, pds,  1.f);
    else if (z == 1) gemm_fp16(g_xh, g_wth[1], g_kh, 1, 0, 0, K_SCALE_F);
    else             gemm_fp16(g_xh, g_wth[2], g_vh, 1, 0, 0, 1.f);
}

__global__ __launch_bounds__(256, 2) void post_gemm(float* __restrict__ out)
{
    gemm_fp16(g_aoh, g_wth[3], out, 0, 0, 0, 1.f);
}

// ------ attention: quad of 4 chunks per CTA; 2 pair-parallel warp groups --
#define QPITCH 136
#define KPITCH 136
#define PPITCH 40
#define AT_SLOG 0                          // float [2][512]
#define AT_SBD  4096                       // float [2][512]
#define AT_QS   8192                       // half 64 x QPITCH
#define AT_KS   (AT_QS + 64*QPITCH*2)      // half 60 x KPITCH
#define AT_VS   (AT_KS + 60*KPITCH*2)      // half 68 x KPITCH
#define AT_RS   (AT_VS + 68*KPITCH*2)      // half 32 x KPITCH
#define AT_PS   (AT_RS + 32*KPITCH*2)      // half [2][16][PPITCH]
#define ATTN_SMEM (AT_PS + 2*16*PPITCH*2)  // 71680

__global__ __launch_bounds__(256) void attn_kernel()
{
    float*  slog = (float*)(dynpool + AT_SLOG);
    float*  sbd  = (float*)(dynpool + AT_SBD);
    __half* qs   = (__half*)(dynpool + AT_QS);
    __half* ks   = (__half*)(dynpool + AT_KS);
    __half* vs   = (__half*)(dynpool + AT_VS);
    __half* rs   = (__half*)(dynpool + AT_RS);
    __half* ps   = (__half*)(dynpool + AT_PS);

    const int bid = blockIdx.x;
    const int h  = bid & 7;
    const int q4 = (bid >> 3) % NQUAD;
    const int b  = bid / (8 * NQUAD);
    const int t  = threadIdx.x;
    const int lane = t & 31;
    const int warp = t >> 5;
    const int wr = warp & 3;
    const int wg = warp >> 2;
    const int lt = t & 127;
    const int g  = lane >> 2;
    const int tg = lane & 3;

    const size_t base = (size_t)b * SEQ * HS + (size_t)h * HD;
    const int r0g = q4 * 48;
    const int s0  = r0g - PASTQ;

    for (int f = t; f < 48 * 16; f += 256) {
        int i = f >> 4, c = (f & 15) << 3;
        int chunk = i / 12, r = i - chunk * 12;
        *(int4*)&qs[(chunk * 16 + r) * QPITCH + c] =
            *(const int4*)&g_qh[base + (size_t)(r0g + i) * HS + c];
    }
    for (int f = t; f < 60 * 16; f += 256) {
        int j = f >> 4, c = (f & 15) << 3;
        int s = s0 + j;
        int4 kv = make_int4(0, 0, 0, 0);
        int4 vv = make_int4(0, 0, 0, 0);
        if (s >= 0) {
            kv = *(const int4*)&g_kh[base + (size_t)s * HS + c];
            vv = *(const int4*)&g_vh[base + (size_t)s * HS + c];
        }
        *(int4*)&ks[j * KPITCH + c] = kv;
        *(int4*)&vs[j * KPITCH + c] = vv;
    }
    {
        int4* v4 = (int4*)(vs + 60 * KPITCH);
        int4 z = make_int4(0, 0, 0, 0);
        for (int f = t; f < 8 * KPITCH / 8; f += 256) v4[f] = z;
    }
    for (int f = t; f < PQ * 16; f += 256) {
        int pp = f >> 4, c = (f & 15) << 3;
        *(int4*)&rs[pp * KPITCH + c] =
            *(const int4*)&g_relkh[(size_t)pp * HS + (size_t)h * HD + c];
    }
    __syncthreads();

    const int aRow = (lane & 7) + ((lane >> 3) & 1) * 8;
    const int aCol = ((lane >> 4) & 1) * 8;
    const int bR   = lane & 7;
    const int bSel = ((lane >> 3) & 1) * 8;
    const int vr   = lane & 15;
    const int barid = 1 + wg;

    float*  slogp = slog + wg * 512;
    float*  sbdp  = sbd  + wg * 512;
    __half* psp   = ps   + wg * 16 * PPITCH;

#pragma unroll
    for (int cl = 0; cl < 2; cl++) {
        const int ci = 2 * wg + cl;
        const __half* qb = qs + ci * 16 * QPITCH;
        const __half* kb = ks + ci * 12 * KPITCH;
        const __half* vb = vs + ci * 12 * KPITCH;

        // scores
        {
            float cac[4] = {0.f, 0.f, 0.f, 0.f};
            float cbd[4] = {0.f, 0.f, 0.f, 0.f};
#pragma unroll
            for (int kh = 0; kh < HD; kh += 16) {
                unsigned a0, a1, a2, a3;
                ldm_x4(a0, a1, a2, a3, cvta_smem(&qb[aRow * QPITCH + kh + aCol]));
                unsigned r0, r1;
                ldm_x2(r0, r1, cvta_smem(&rs[(8 * wr + bR) * KPITCH + kh + bSel]));
                mma16816(cbd, a0, a1, a2, a3, r0, r1);
                if (wr < 3) {
                    unsigned k0, k1;
                    ldm_x2(k0, k1, cvta_smem(&kb[(8 * wr + bR) * KPITCH + kh + bSel]));
                    mma16816(cac, a0, a1, a2, a3, k0, k1);
                }
            }
            int c0 = 8 * wr + 2 * tg;
            if (wr < 3) {
                slogp[g * 32 + c0]           = cac[0];
                slogp[g * 32 + c0 + 1]       = cac[1];
                slogp[(g + 8) * 32 + c0]     = cac[2];
                slogp[(g + 8) * 32 + c0 + 1] = cac[3];
            }
            sbdp[g * 32 + c0]           = cbd[0];
            sbdp[g * 32 + c0 + 1]       = cbd[1];
            sbdp[(g + 8) * 32 + c0]     = cbd[2];
            sbdp[(g + 8) * 32 + c0 + 1] = cbd[3];
        }
        BARS(barid);

        // rel-shift + softcap
        for (int e = lt; e < CHUNKQ * CTXQ; e += 128) {
            int i = e / CTXQ, j = e % CTXQ;
            float val = slogp[i * 32 + j] + sbdp[(e / PQ) * 32 + (e % PQ)];
            slogp[i * 32 + j] = tanhf(val * (1.0f / 50.0f)) * 50.0f;
        }
        BARS(barid);

        // softmax rows 0-11; P cols 0-23 + explicit zeros 24-31
        if (lt < CHUNKQ) {
            float m = -1e30f;
#pragma unroll
            for (int j = 0; j < CTXQ; j++) m = fmaxf(m, slogp[lt * 32 + j]);
            float s = 0.f;
            float e_[CTXQ];
#pragma unroll
            for (int j = 0; j < CTXQ; j++) {
                e_[j] = __expf(slogp[lt * 32 + j] - m);
                s += e_[j];
            }
            float inv = 1.0f / s;
#pragma unroll
            for (int j = 0; j < CTXQ; j += 2)
                *(__half2*)&psp[lt * PPITCH + j] =
                    __floats2half2_rn(e_[j] * inv, e_[j + 1] * inv);
            __half2 hz = __floats2half2_rn(0.f, 0.f);
#pragma unroll
            for (int j = CTXQ; j < 32; j += 2)
                *(__half2*)&psp[lt * PPITCH + j] = hz;
        }
        BARS(barid);

        // out = P @ V
        {
            unsigned qa[8];
            ldm_x4(qa[0], qa[1], qa[2], qa[3],
                   cvta_smem(&psp[aRow * PPITCH + aCol]));
            ldm_x4(qa[4], qa[5], qa[6], qa[7],
                   cvta_smem(&psp[aRow * PPITCH + 16 + aCol]));
#pragma unroll
            for (int nt = 0; nt < 4; nt++) {
                int n0 = 32 * wr + 8 * nt;
                float co[4] = {0.f, 0.f, 0.f, 0.f};
                unsigned v0, v1;
                ldm_x2_trans(v0, v1, cvta_smem(&vb[vr * KPITCH + n0]));
                mma16816(co, qa[0], qa[1], qa[2], qa[3], v0, v1);
                ldm_x2_trans(v0, v1, cvta_smem(&vb[(16 + vr) * KPITCH + n0]));
                mma16816(co, qa[4], qa[5], qa[6], qa[7], v0, v1);

                int d0 = n0 + 2 * tg;
                int row0 = r0g + ci * 12 + g;
                *(__half2*)&g_aoh[base + (size_t)row0 * HS + d0] =
                    __floats2half2_rn(co[0], co[1]);
                if (g < 4)
                    *(__half2*)&g_aoh[base + (size_t)(row0 + 8) * HS + d0] =
                        __floats2half2_rn(co[2], co[3]);
            }
        }
        BARS(barid);   // protect slogp/sbdp/psp before next chunk
    }
}

// ---------------- launch ----------------
extern "C" void kernel_launch(void* const* d_in, const int* in_sizes, int n_in,
                              void* d_out, int out_size)
{
    const float* x     = (const float*)d_in[0];
    const float* pe    = (const float*)d_in[1];
    const float* Wq    = (const float*)d_in[2];
    const float* Wk    = (const float*)d_in[3];
    const float* Wv    = (const float*)d_in[4];
    const float* Wpost = (const float*)d_in[5];
    const float* Wrel  = (const float*)d_in[6];
    const float* pds   = (const float*)d_in[7];
    float* out = (float*)d_out;

    static int configured = 0;
    if (!configured) {
        cudaFuncSetAttribute(qkv_gemm,
            cudaFuncAttributeMaxDynamicSharedMemorySize, SMEM_DYN);
        cudaFuncSetAttribute(post_gemm,
            cudaFuncAttributeMaxDynamicSharedMemorySize, SMEM_DYN);
        cudaFuncSetAttribute(attn_kernel,
            cudaFuncAttributeMaxDynamicSharedMemorySize, ATTN_SMEM);
        configured = 1;
    }

    prep_all<<<XBLOCKS + 4096, 256>>>(x, Wq, Wk, Wv, Wpost);

    dim3 gq(HS / BN, MROWS / BM, 4);
    qkv_gemm<<<gq, 256, SMEM_DYN>>>(pds, pe, Wrel);

    relk_half<<<PQ * HS / 256, 256>>>();

    attn_kernel<<<BATCH * NQUAD * NH, 256, ATTN_SMEM>>>();

    dim3 gp(HS / BN, MROWS / BM);
    post_gemm<<<gp, 256, SMEM_DYN>>>(out);
}